// round 1
// baseline (speedup 1.0000x reference)
#include <cuda_runtime.h>
#include <cstdint>

#define TT 16384
#define CC 1024
#define W_MAX 1024
#define N_ITERS 30
#define NPART 16   // i-chunks for u partial sums

__device__ float g_qlast[CC];
__device__ float g_upart[NPART * CC];
__device__ float g_att[TT];
__device__ float g_av[TT];
__device__ float4 g_stats[W_MAX + 1];   // per window w: (m, s, sum e*count, sum e*av)

__device__ __forceinline__ float neg_inf() { return __int_as_float(0xff800000); }

// ---------------------------------------------------------------------------
// K1: q_last[i] = dot(x[T-1,:], W[i,:])  for i in [0,1024). One warp per row.
// ---------------------------------------------------------------------------
__global__ void k_qlast(const float* __restrict__ x, const float* __restrict__ W) {
    int warp = (blockIdx.x * blockDim.x + threadIdx.x) >> 5;
    int lane = threadIdx.x & 31;
    if (warp >= CC) return;
    const float4* xl = (const float4*)(x + (size_t)(TT - 1) * CC);
    const float4* wr = (const float4*)(W + (size_t)warp * CC);
    float s = 0.f;
#pragma unroll
    for (int c = 0; c < 8; c++) {
        float4 a = xl[c * 32 + lane];
        float4 b = wr[c * 32 + lane];
        s += a.x * b.x + a.y * b.y + a.z * b.z + a.w * b.w;
    }
#pragma unroll
    for (int o = 16; o; o >>= 1) s += __shfl_xor_sync(0xffffffffu, s, o);
    if (lane == 0) g_qlast[warp] = s;
}

// ---------------------------------------------------------------------------
// K2: partial sums of u[j] = sum_i q_last[i] * W_k[i, j].
// grid = 4 j-chunks * NPART i-chunks. Deterministic (no atomics).
// ---------------------------------------------------------------------------
__global__ void k_upart(const float* __restrict__ W) {
    int jc = blockIdx.x & 3;
    int ic = blockIdx.x >> 2;          // 0..NPART-1
    int j  = jc * 256 + threadIdx.x;
    const float* Wk = W + (size_t)CC * CC;
    const int ilen = CC / NPART;       // 64
    int i0 = ic * ilen;
    float s = 0.f;
#pragma unroll 8
    for (int i = 0; i < ilen; i++) {
        s += g_qlast[i0 + i] * Wk[(size_t)(i0 + i) * CC + j];
    }
    g_upart[ic * CC + j] = s;
}

// ---------------------------------------------------------------------------
// K3: per-row dual GEMV:  att[t] = scale * u.x[t],  av[t] = w_v.x[t].
// u assembled from partials in each block's prologue (L2-hot). One warp/row.
// ---------------------------------------------------------------------------
__global__ void k_att(const float* __restrict__ x, const float* __restrict__ W) {
    __shared__ float su[CC];
    __shared__ float sv[CC];
    const float* wv = W + (size_t)(2 * CC) * CC;   // row 2048
    for (int j = threadIdx.x; j < CC; j += blockDim.x) {
        float s = 0.f;
#pragma unroll
        for (int p = 0; p < NPART; p++) s += g_upart[p * CC + j];
        su[j] = s;
        sv[j] = wv[j];
    }
    __syncthreads();

    const float SCALE = (float)(0.001 / 32.0);   // 0.001/sqrt(1024)
    int warp = threadIdx.x >> 5, lane = threadIdx.x & 31;
    int wglobal = blockIdx.x * (blockDim.x >> 5) + warp;
    int nwarps  = gridDim.x * (blockDim.x >> 5);
    const float4* su4 = (const float4*)su;
    const float4* sv4 = (const float4*)sv;

    for (int row = wglobal; row < TT; row += nwarps) {
        const float4* xr = (const float4*)(x + (size_t)row * CC);
        float du = 0.f, dv = 0.f;
#pragma unroll
        for (int c = 0; c < 8; c++) {
            float4 a = xr[c * 32 + lane];
            float4 b = su4[c * 32 + lane];
            float4 v = sv4[c * 32 + lane];
            du += a.x * b.x + a.y * b.y + a.z * b.z + a.w * b.w;
            dv += a.x * v.x + a.y * v.y + a.z * v.z + a.w * v.w;
        }
#pragma unroll
        for (int o = 16; o; o >>= 1) {
            du += __shfl_xor_sync(0xffffffffu, du, o);
            dv += __shfl_xor_sync(0xffffffffu, dv, o);
        }
        if (lane == 0) {
            g_att[row] = (row == TT - 1) ? neg_inf() : du * SCALE;
            g_av[row]  = dv;
        }
    }
}

// ---------------------------------------------------------------------------
// K4a: precompute softmax stats for every window size w in [1, W_MAX].
// One warp per w. Window = last w positions; count at t is (T-1-t) = l,
// where l is distance from the end.
// ---------------------------------------------------------------------------
__global__ void k_stats() {
    int w = blockIdx.x * (blockDim.x >> 5) + (threadIdx.x >> 5) + 1;
    int lane = threadIdx.x & 31;
    if (w > W_MAX) return;
    float m = neg_inf();
    for (int l = lane; l < w; l += 32) m = fmaxf(m, g_att[TT - 1 - l]);
#pragma unroll
    for (int o = 16; o; o >>= 1) m = fmaxf(m, __shfl_xor_sync(0xffffffffu, m, o));
    float s = 0.f, bs = 0.f, ys = 0.f;
    for (int l = lane; l < w; l += 32) {
        float e = expf(g_att[TT - 1 - l] - m);
        s  += e;
        bs += e * (float)l;
        ys += e * g_av[TT - 1 - l];
    }
#pragma unroll
    for (int o = 16; o; o >>= 1) {
        s  += __shfl_xor_sync(0xffffffffu, s, o);
        bs += __shfl_xor_sync(0xffffffffu, bs, o);
        ys += __shfl_xor_sync(0xffffffffu, ys, o);
    }
    if (lane == 0) g_stats[w] = make_float4(m, s, bs, ys);
}

// ---------------------------------------------------------------------------
// K4b: the serial 30-iteration scan. All threads run the identical scalar
// recurrence; stats come from the table (normal path) or a cooperative
// block reduction (fallback for w > W_MAX). Thread 0 writes the output.
// ---------------------------------------------------------------------------
__device__ float blk_reduce(float v, int is_max, float* red) {
    int lane = threadIdx.x & 31, wid = threadIdx.x >> 5;
#pragma unroll
    for (int o = 16; o; o >>= 1) {
        float t = __shfl_xor_sync(0xffffffffu, v, o);
        v = is_max ? fmaxf(v, t) : v + t;
    }
    if (lane == 0) red[wid] = v;
    __syncthreads();
    int nw = blockDim.x >> 5;
    if (wid == 0) {
        float t = (lane < nw) ? red[lane] : (is_max ? neg_inf() : 0.f);
#pragma unroll
        for (int o = 16; o; o >>= 1) {
            float u = __shfl_xor_sync(0xffffffffu, t, o);
            t = is_max ? fmaxf(t, u) : t + u;
        }
        if (lane == 0) red[0] = t;
    }
    __syncthreads();
    float r = red[0];
    __syncthreads();
    return r;
}

__global__ void k_scan(const float* __restrict__ alpha,
                       const float* __restrict__ beta,
                       float* __restrict__ out) {
    __shared__ float red[32];
    float a = *alpha, b = *beta, k_old = 0.f, y = 0.f;
    for (int it = 0; it < N_ITERS; it++) {
        float kk = 2.f * (a + b) / a;
        float wf = ceilf(kk);
        int w = (wf >= (float)TT) ? TT : (int)wf;
        if (w < 1) w = 1;
        float m, s, bs, ys;
        if (w <= W_MAX) {
            float4 st = g_stats[w];
            m = st.x; s = st.y; bs = st.z; ys = st.w;
        } else {
            float lm = neg_inf();
            for (int l = threadIdx.x; l < w; l += blockDim.x)
                lm = fmaxf(lm, g_att[TT - 1 - l]);
            m = blk_reduce(lm, 1, red);
            float ls = 0.f, lb = 0.f, ly = 0.f;
            for (int l = threadIdx.x; l < w; l += blockDim.x) {
                float e = expf(g_att[TT - 1 - l] - m);
                ls += e;
                lb += e * (float)l;
                ly += e * g_av[TT - 1 - l];
            }
            s  = blk_reduce(ls, 0, red);
            bs = blk_reduce(lb, 0, red);
            ys = blk_reduce(ly, 0, red);
        }
        float bu = bs / s;
        y = ys / s;
        a += 1.f;
        b += bu;
        bool stop = (kk > (float)TT) || (kk < k_old);
        k_old = kk;
        if (stop) break;
    }
    if (threadIdx.x == 0) out[0] = y;
}

// ---------------------------------------------------------------------------
extern "C" void kernel_launch(void* const* d_in, const int* in_sizes, int n_in,
                              void* d_out, int out_size) {
    const float* x = nullptr;
    const float* W = nullptr;
    const float* alpha = nullptr;
    const float* beta = nullptr;
    for (int i = 0; i < n_in; i++) {
        if (in_sizes[i] == TT * CC)                x = (const float*)d_in[i];
        else if (in_sizes[i] == (2 * CC + 1) * CC) W = (const float*)d_in[i];
        else if (in_sizes[i] == 1) {
            if (!alpha) alpha = (const float*)d_in[i];
            else        beta  = (const float*)d_in[i];
        }
    }
    float* out = (float*)d_out;

    k_qlast<<<128, 256>>>(x, W);          // 1024 warps, one per W_q row
    k_upart<<<4 * NPART, 256>>>(W);       // u partials over W_k
    k_att  <<<512, 256>>>(x, W);          // dual GEMV over x (the 64 MB pass)
    k_stats<<<W_MAX / 8, 256>>>();        // one warp per window size
    k_scan <<<1, 256>>>(alpha, beta, out);
}

// round 3
// speedup vs baseline: 1.3407x; 1.3407x over previous
#include <cuda_runtime.h>
#include <cstdint>

#define TT 16384
#define CC 1024
#define NROWS 2048          // tail rows with precomputed att/av (window stays ~12-17)
#define N_ITERS 30
#define NPART 32            // i-chunks for u partial sums
#define BLK 1024            // threads in k_final

__device__ float g_qlast[CC];
__device__ float g_upart[NPART * CC];
__device__ float g_u[CC];
__device__ float g_att[TT];
__device__ float g_av[TT];

__device__ __forceinline__ float neg_inf() { return __int_as_float(0xff800000); }

#define SCALE 3.125e-5f     // 0.001 / sqrt(1024)

// ---------------------------------------------------------------------------
// K1: q_last[i] = dot(x[T-1,:], W_q[i,:]).  One warp per row i.
// ---------------------------------------------------------------------------
__global__ void __launch_bounds__(256) k_qlast(const float* __restrict__ x,
                                               const float* __restrict__ W) {
    int warp = (blockIdx.x * blockDim.x + threadIdx.x) >> 5;
    int lane = threadIdx.x & 31;
    if (warp >= CC) return;
    const float4* xl = (const float4*)(x + (size_t)(TT - 1) * CC);
    const float4* wr = (const float4*)(W + (size_t)warp * CC);
    float s = 0.f;
#pragma unroll
    for (int c = 0; c < 8; c++) {
        float4 a = xl[c * 32 + lane];
        float4 b = wr[c * 32 + lane];
        s += a.x * b.x + a.y * b.y + a.z * b.z + a.w * b.w;
    }
#pragma unroll
    for (int o = 16; o; o >>= 1) s += __shfl_xor_sync(0xffffffffu, s, o);
    if (lane == 0) g_qlast[warp] = s;
}

// ---------------------------------------------------------------------------
// K2: partial sums of u[j] = sum_i q_last[i] * W_k[i, j].  Deterministic.
// ---------------------------------------------------------------------------
__global__ void __launch_bounds__(256) k_upart(const float* __restrict__ W) {
    int jc = blockIdx.x & 3;
    int ic = blockIdx.x >> 2;              // 0..NPART-1
    int j  = jc * 256 + threadIdx.x;
    const float* Wk = W + (size_t)CC * CC;
    const int ilen = CC / NPART;           // 32
    int i0 = ic * ilen;
    float s = 0.f;
#pragma unroll
    for (int i = 0; i < ilen; i++)
        s += g_qlast[i0 + i] * Wk[(size_t)(i0 + i) * CC + j];
    g_upart[ic * CC + j] = s;
}

// K2b: reduce partials -> g_u
__global__ void __launch_bounds__(CC) k_ured() {
    int t = threadIdx.x;
    float s = 0.f;
#pragma unroll
    for (int p = 0; p < NPART; p++) s += g_upart[p * CC + t];
    g_u[t] = s;
}

// ---------------------------------------------------------------------------
// K3: dual GEMV over the LAST NROWS rows only:
//     att[t] = SCALE * u.x[t],  av[t] = w_v.x[t].  One warp per row.
// ---------------------------------------------------------------------------
__global__ void __launch_bounds__(256) k_att2(const float* __restrict__ x,
                                              const float* __restrict__ W) {
    __shared__ float su[CC];
    __shared__ float sv[CC];
    const float* wv = W + (size_t)(2 * CC) * CC;
    for (int j = threadIdx.x; j < CC; j += blockDim.x) { su[j] = g_u[j]; sv[j] = wv[j]; }
    __syncthreads();

    int wid = threadIdx.x >> 5, lane = threadIdx.x & 31;
    int wg  = blockIdx.x * (blockDim.x >> 5) + wid;      // 0..NROWS-1
    int row = TT - NROWS + wg;
    const float4* xr  = (const float4*)(x + (size_t)row * CC);
    const float4* su4 = (const float4*)su;
    const float4* sv4 = (const float4*)sv;
    float du = 0.f, dv = 0.f;
#pragma unroll
    for (int c = 0; c < 8; c++) {
        float4 a = xr[c * 32 + lane];
        float4 b = su4[c * 32 + lane];
        float4 v = sv4[c * 32 + lane];
        du += a.x * b.x + a.y * b.y + a.z * b.z + a.w * b.w;
        dv += a.x * v.x + a.y * v.y + a.z * v.z + a.w * v.w;
    }
#pragma unroll
    for (int o = 16; o; o >>= 1) {
        du += __shfl_xor_sync(0xffffffffu, du, o);
        dv += __shfl_xor_sync(0xffffffffu, dv, o);
    }
    if (lane == 0) {
        g_att[row] = (row == TT - 1) ? neg_inf() : du * SCALE;
        g_av[row]  = dv;
    }
}

// ---------------------------------------------------------------------------
// K4: fused stats (prefix scan over tail, single global max) + serial scan.
// One block of 1024 threads; each thread owns 2 tail positions.
// __launch_bounds__(1024,1) caps regs at 64 (fallback path spills — never taken).
// ---------------------------------------------------------------------------
__device__ float blk_reduce(float v, int is_max, float* red) {
    int lane = threadIdx.x & 31, wid = threadIdx.x >> 5;
#pragma unroll
    for (int o = 16; o; o >>= 1) {
        float t = __shfl_xor_sync(0xffffffffu, v, o);
        v = is_max ? fmaxf(v, t) : v + t;
    }
    if (lane == 0) red[wid] = v;
    __syncthreads();
    if (wid == 0) {
        float t = red[lane];
#pragma unroll
        for (int o = 16; o; o >>= 1) {
            float u = __shfl_xor_sync(0xffffffffu, t, o);
            t = is_max ? fmaxf(t, u) : t + u;
        }
        if (lane == 0) red[0] = t;
    }
    __syncthreads();
    float r = red[0];
    __syncthreads();
    return r;
}

__global__ void __launch_bounds__(BLK, 1)
k_final(const float* __restrict__ x, const float* __restrict__ W,
        const float* __restrict__ alpha, const float* __restrict__ beta,
        float* __restrict__ out) {
    __shared__ float sS[NROWS + 2], sB[NROWS + 2], sY[NROWS + 2];
    __shared__ float su[CC], sv[CC];
    __shared__ float wS[32], wB[32], wY[32];
    __shared__ float red[32];
    __shared__ float smax;

    int t = threadIdx.x, lane = t & 31, wid = t >> 5;

    // u, wv for the (never-taken) deep fallback
    const float* wv = W + (size_t)(2 * CC) * CC;
    su[t] = g_u[t];
    sv[t] = wv[t];

    // --- load tail pair, global max ---
    int l0 = 2 * t;
    float a0 = g_att[TT - 1 - l0];
    float a1 = g_att[TT - 2 - l0];
    float v0 = g_av[TT - 1 - l0];
    float v1 = g_av[TT - 2 - l0];

    float lm = fmaxf(a0, a1);
    float m = blk_reduce(lm, 1, red);
    if (t == 0) smax = m;
    __syncthreads();
    m = smax;

    // --- per-thread pair contributions ---
    float e0 = expf(a0 - m), e1 = expf(a1 - m);
    float ps = e0 + e1;
    float pb = e0 * (float)l0 + e1 * (float)(l0 + 1);
    float py = e0 * v0 + e1 * v1;

    // --- block inclusive scan of (ps, pb, py) ---
#pragma unroll
    for (int o = 1; o < 32; o <<= 1) {
        float ts = __shfl_up_sync(0xffffffffu, ps, o);
        float tb = __shfl_up_sync(0xffffffffu, pb, o);
        float ty = __shfl_up_sync(0xffffffffu, py, o);
        if (lane >= o) { ps += ts; pb += tb; py += ty; }
    }
    if (lane == 31) { wS[wid] = ps; wB[wid] = pb; wY[wid] = py; }
    __syncthreads();
    if (wid == 0) {
        float vs = wS[lane], vb = wB[lane], vy = wY[lane];
#pragma unroll
        for (int o = 1; o < 32; o <<= 1) {
            float ts = __shfl_up_sync(0xffffffffu, vs, o);
            float tb = __shfl_up_sync(0xffffffffu, vb, o);
            float ty = __shfl_up_sync(0xffffffffu, vy, o);
            if (lane >= o) { vs += ts; vb += tb; vy += ty; }
        }
        wS[lane] = vs; wB[lane] = vb; wY[lane] = vy;
    }
    __syncthreads();
    if (wid > 0) { ps += wS[wid - 1]; pb += wB[wid - 1]; py += wY[wid - 1]; }

    // table: sS[w] = sum over last w positions (l = 0..w-1)
    sS[l0 + 2] = ps;                        sS[l0 + 1] = ps - e1;
    sB[l0 + 2] = pb;                        sB[l0 + 1] = pb - e1 * (float)(l0 + 1);
    sY[l0 + 2] = py;                        sY[l0 + 1] = py - e1 * v1;
    if (t == 0) { sS[0] = 0.f; sB[0] = 0.f; sY[0] = 0.f; }
    __syncthreads();

    // --- serial 30-iteration recurrence (all threads redundantly) ---
    const float4* su4 = (const float4*)su;
    const float4* sv4 = (const float4*)sv;
    float a = *alpha, b = *beta, k_old = 0.f, y = 0.f;

    for (int it = 0; it < N_ITERS; it++) {
        float kk = 2.f * (a + b) / a;
        float wf = ceilf(kk);
        int w = (wf >= (float)TT) ? TT : (int)wf;
        if (w < 1) w = 1;

        float s, bs, ys;
        if (w <= NROWS) {
            s = sS[w]; bs = sB[w]; ys = sY[w];
        } else {
            // Deep fallback (not taken for these inputs): extend att/av, then reduce.
            for (int l = NROWS + wid; l < w; l += 32) {
                const float4* xr = (const float4*)(x + (size_t)(TT - 1 - l) * CC);
                float du = 0.f, dv = 0.f;
#pragma unroll 4
                for (int c = 0; c < 8; c++) {
                    float4 xa = xr[c * 32 + lane];
                    float4 ub = su4[c * 32 + lane];
                    float4 vb = sv4[c * 32 + lane];
                    du += xa.x * ub.x + xa.y * ub.y + xa.z * ub.z + xa.w * ub.w;
                    dv += xa.x * vb.x + xa.y * vb.y + xa.z * vb.z + xa.w * vb.w;
                }
#pragma unroll
                for (int o = 16; o; o >>= 1) {
                    du += __shfl_xor_sync(0xffffffffu, du, o);
                    dv += __shfl_xor_sync(0xffffffffu, dv, o);
                }
                if (lane == 0) { g_att[TT - 1 - l] = du * SCALE; g_av[TT - 1 - l] = dv; }
            }
            __syncthreads();
            float lmx = neg_inf();
            for (int l = t; l < w; l += BLK) lmx = fmaxf(lmx, g_att[TT - 1 - l]);
            float m2 = blk_reduce(lmx, 1, red);
            float ls = 0.f, lb = 0.f, ly = 0.f;
            for (int l = t; l < w; l += BLK) {
                float e = expf(g_att[TT - 1 - l] - m2);
                ls += e; lb += e * (float)l; ly += e * g_av[TT - 1 - l];
            }
            s  = blk_reduce(ls, 0, red);
            bs = blk_reduce(lb, 0, red);
            ys = blk_reduce(ly, 0, red);
        }

        float bu = bs / s;
        y = ys / s;
        a += 1.f;
        b += bu;
        bool stop = (kk > (float)TT) || (kk < k_old);
        k_old = kk;
        if (stop) break;
    }
    if (t == 0) out[0] = y;
}

// ---------------------------------------------------------------------------
extern "C" void kernel_launch(void* const* d_in, const int* in_sizes, int n_in,
                              void* d_out, int out_size) {
    const float* x = nullptr;
    const float* W = nullptr;
    const float* alpha = nullptr;
    const float* beta = nullptr;
    for (int i = 0; i < n_in; i++) {
        if (in_sizes[i] == TT * CC)                x = (const float*)d_in[i];
        else if (in_sizes[i] == (2 * CC + 1) * CC) W = (const float*)d_in[i];
        else if (in_sizes[i] == 1) {
            if (!alpha) alpha = (const float*)d_in[i];
            else        beta  = (const float*)d_in[i];
        }
    }
    float* out = (float*)d_out;

    k_qlast<<<128, 256>>>(x, W);              // W_q GEMV (4 MB)
    k_upart<<<4 * NPART, 256>>>(W);           // W_k^T partials (4 MB)
    k_ured <<<1, CC>>>();                      // partials -> u
    k_att2 <<<NROWS / 8, 256>>>(x, W);        // tail dual GEMV (8 MB)
    k_final<<<1, BLK>>>(x, W, alpha, beta, out);
}

// round 4
// speedup vs baseline: 1.6486x; 1.2297x over previous
#include <cuda_runtime.h>
#include <cstdint>

#define TT 16384
#define CC 1024
#define NROWS 128           // tail rows with precomputed att/av (window provably ~19)
#define N_ITERS 30
#define NPART 16            // i-chunks for u partial sums
#define BLK 128             // threads in k_final

__device__ float g_qlast[CC];
__device__ float g_upart[NPART * CC];
__device__ float g_att[TT];
__device__ float g_av[TT];

__device__ __forceinline__ float neg_inf() { return __int_as_float(0xff800000); }

#define SCALE 3.125e-5f     // 0.001 / sqrt(1024)

// ---------------------------------------------------------------------------
// K1: q_last[i] = dot(x[T-1,:], W_q[i,:]).  One warp per row i.
// 256 blocks x 128 thr = 1024 warps -> all 148 SMs busy.
// ---------------------------------------------------------------------------
__global__ void __launch_bounds__(128) k_qlast(const float* __restrict__ x,
                                               const float* __restrict__ W) {
    int warp = (blockIdx.x * blockDim.x + threadIdx.x) >> 5;
    int lane = threadIdx.x & 31;
    const float4* xl = (const float4*)(x + (size_t)(TT - 1) * CC);
    const float4* wr = (const float4*)(W + (size_t)warp * CC);
    float s = 0.f;
#pragma unroll
    for (int c = 0; c < 8; c++) {
        float4 a = xl[c * 32 + lane];
        float4 b = wr[c * 32 + lane];
        s += a.x * b.x + a.y * b.y + a.z * b.z + a.w * b.w;
    }
#pragma unroll
    for (int o = 16; o; o >>= 1) s += __shfl_xor_sync(0xffffffffu, s, o);
    if (lane == 0) g_qlast[warp] = s;
}

// ---------------------------------------------------------------------------
// K2: partial sums of u[j] = sum_i q_last[i] * W_k[i, j].  Deterministic.
// 128 blocks x 128 thr; 64 independent loads per thread (high MLP).
// ---------------------------------------------------------------------------
__global__ void __launch_bounds__(128) k_upart(const float* __restrict__ W) {
    int jc = blockIdx.x & 7;               // 8 j-chunks of 128
    int ic = blockIdx.x >> 3;              // 0..NPART-1
    int j  = jc * 128 + threadIdx.x;
    const float* Wk = W + (size_t)CC * CC;
    const int ilen = CC / NPART;           // 64
    int i0 = ic * ilen;
    float s = 0.f;
#pragma unroll 8
    for (int i = 0; i < ilen; i++)
        s += g_qlast[i0 + i] * Wk[(size_t)(i0 + i) * CC + j];
    g_upart[ic * CC + j] = s;
}

// ---------------------------------------------------------------------------
// K3: dual GEMV over the LAST NROWS rows. Prologue folds the u-reduction
// (redundant per block, L2-hot). One warp per row; 16 blocks x 8 warps.
// ---------------------------------------------------------------------------
__global__ void __launch_bounds__(256) k_att(const float* __restrict__ x,
                                             const float* __restrict__ W) {
    __shared__ float su[CC];
    __shared__ float sv[CC];
    const float* wv = W + (size_t)(2 * CC) * CC;
    for (int j = threadIdx.x; j < CC; j += 256) {
        float s = 0.f;
#pragma unroll
        for (int p = 0; p < NPART; p++) s += g_upart[p * CC + j];
        su[j] = s;
        sv[j] = wv[j];
    }
    __syncthreads();

    int wid = threadIdx.x >> 5, lane = threadIdx.x & 31;
    int r   = blockIdx.x * 8 + wid;                    // 0..NROWS-1
    int row = TT - NROWS + r;
    const float4* xr  = (const float4*)(x + (size_t)row * CC);
    const float4* su4 = (const float4*)su;
    const float4* sv4 = (const float4*)sv;
    float du = 0.f, dv = 0.f;
#pragma unroll
    for (int c = 0; c < 8; c++) {
        float4 a = xr[c * 32 + lane];
        float4 b = su4[c * 32 + lane];
        float4 v = sv4[c * 32 + lane];
        du += a.x * b.x + a.y * b.y + a.z * b.z + a.w * b.w;
        dv += a.x * v.x + a.y * v.y + a.z * v.z + a.w * v.w;
    }
#pragma unroll
    for (int o = 16; o; o >>= 1) {
        du += __shfl_xor_sync(0xffffffffu, du, o);
        dv += __shfl_xor_sync(0xffffffffu, dv, o);
    }
    if (lane == 0) {
        g_att[row] = (row == TT - 1) ? neg_inf() : du * SCALE;
        g_av[row]  = dv;
    }
}

// ---------------------------------------------------------------------------
// K4: fused stats (prefix scan over tail, single global max) + serial scan.
// 128 threads, one tail position each. Fallback (never taken for these
// inputs) recomputes deeper windows exactly.
// ---------------------------------------------------------------------------
__device__ float blk_reduce(float v, int is_max, float* red) {
    int lane = threadIdx.x & 31, wid = threadIdx.x >> 5;
    const int nw = BLK / 32;
#pragma unroll
    for (int o = 16; o; o >>= 1) {
        float t = __shfl_xor_sync(0xffffffffu, v, o);
        v = is_max ? fmaxf(v, t) : v + t;
    }
    if (lane == 0) red[wid] = v;
    __syncthreads();
    if (wid == 0) {
        float t = (lane < nw) ? red[lane] : (is_max ? neg_inf() : 0.f);
#pragma unroll
        for (int o = 16; o; o >>= 1) {
            float u = __shfl_xor_sync(0xffffffffu, t, o);
            t = is_max ? fmaxf(t, u) : t + u;
        }
        if (lane == 0) red[0] = t;
    }
    __syncthreads();
    float r = red[0];
    __syncthreads();
    return r;
}

__global__ void __launch_bounds__(BLK, 1)
k_final(const float* __restrict__ x, const float* __restrict__ W,
        const float* __restrict__ alpha, const float* __restrict__ beta,
        float* __restrict__ out) {
    __shared__ float sS[NROWS + 1], sB[NROWS + 1], sY[NROWS + 1];
    __shared__ float su[CC], sv[CC];
    __shared__ float wS[4], wB[4], wY[4];
    __shared__ float red[32];
    __shared__ float smax;

    int t = threadIdx.x, lane = t & 31, wid = t >> 5;

    // u, wv into shared (used by the never-taken deep fallback)
    const float* wv = W + (size_t)(2 * CC) * CC;
#pragma unroll
    for (int c = 0; c < CC / BLK; c++) {
        int j = c * BLK + t;
        float s = 0.f;
#pragma unroll
        for (int p = 0; p < NPART; p++) s += g_upart[p * CC + j];
        su[j] = s;
        sv[j] = wv[j];
    }

    // --- load tail position l = t, global max ---
    float a0 = g_att[TT - 1 - t];
    float v0 = g_av[TT - 1 - t];
    float m = blk_reduce(a0, 1, red);
    if (t == 0) smax = m;
    __syncthreads();
    m = smax;

    // --- per-position contributions ---
    float e0 = expf(a0 - m);
    float ps = e0;
    float pb = e0 * (float)t;
    float py = e0 * v0;

    // --- block inclusive scan (128 = 4 warps) ---
#pragma unroll
    for (int o = 1; o < 32; o <<= 1) {
        float ts = __shfl_up_sync(0xffffffffu, ps, o);
        float tb = __shfl_up_sync(0xffffffffu, pb, o);
        float ty = __shfl_up_sync(0xffffffffu, py, o);
        if (lane >= o) { ps += ts; pb += tb; py += ty; }
    }
    if (lane == 31) { wS[wid] = ps; wB[wid] = pb; wY[wid] = py; }
    __syncthreads();
    if (t == 0) {
        float cs = 0.f, cb = 0.f, cy = 0.f;
#pragma unroll
        for (int i = 0; i < 4; i++) {
            float ns = wS[i], nb = wB[i], ny = wY[i];
            wS[i] = cs; wB[i] = cb; wY[i] = cy;     // exclusive warp offsets
            cs += ns; cb += nb; cy += ny;
        }
    }
    __syncthreads();
    ps += wS[wid]; pb += wB[wid]; py += wY[wid];

    sS[t + 1] = ps; sB[t + 1] = pb; sY[t + 1] = py;
    if (t == 0) { sS[0] = 0.f; sB[0] = 0.f; sY[0] = 0.f; }
    __syncthreads();

    // --- serial 30-iteration recurrence (all threads redundantly) ---
    const float4* su4 = (const float4*)su;
    const float4* sv4 = (const float4*)sv;
    float a = *alpha, b = *beta, k_old = 0.f, y = 0.f;

    for (int it = 0; it < N_ITERS; it++) {
        float kk = 2.f * (a + b) / a;
        float wf = ceilf(kk);
        int w = (wf >= (float)TT) ? TT : (int)wf;
        if (w < 1) w = 1;

        float s, bs, ys;
        if (w <= NROWS) {
            s = sS[w]; bs = sB[w]; ys = sY[w];
        } else {
            // Deep fallback (not taken for these inputs): extend att/av, reduce.
            for (int l = NROWS + wid; l < w; l += 4) {
                const float4* xr = (const float4*)(x + (size_t)(TT - 1 - l) * CC);
                float du = 0.f, dv = 0.f;
#pragma unroll 4
                for (int c = 0; c < 8; c++) {
                    float4 xa = xr[c * 32 + lane];
                    float4 ub = su4[c * 32 + lane];
                    float4 vb = sv4[c * 32 + lane];
                    du += xa.x * ub.x + xa.y * ub.y + xa.z * ub.z + xa.w * ub.w;
                    dv += xa.x * vb.x + xa.y * vb.y + xa.z * vb.z + xa.w * vb.w;
                }
#pragma unroll
                for (int o = 16; o; o >>= 1) {
                    du += __shfl_xor_sync(0xffffffffu, du, o);
                    dv += __shfl_xor_sync(0xffffffffu, dv, o);
                }
                if (lane == 0) { g_att[TT - 1 - l] = du * SCALE; g_av[TT - 1 - l] = dv; }
            }
            __syncthreads();
            float lmx = neg_inf();
            for (int l = t; l < w; l += BLK) lmx = fmaxf(lmx, g_att[TT - 1 - l]);
            float m2 = blk_reduce(lmx, 1, red);
            float ls = 0.f, lb = 0.f, ly = 0.f;
            for (int l = t; l < w; l += BLK) {
                float e = expf(g_att[TT - 1 - l] - m2);
                ls += e; lb += e * (float)l; ly += e * g_av[TT - 1 - l];
            }
            s  = blk_reduce(ls, 0, red);
            bs = blk_reduce(lb, 0, red);
            ys = blk_reduce(ly, 0, red);
        }

        float bu = bs / s;
        y = ys / s;
        a += 1.f;
        b += bu;
        bool stop = (kk > (float)TT) || (kk < k_old);
        k_old = kk;
        if (stop) break;
    }
    if (t == 0) out[0] = y;
}

// ---------------------------------------------------------------------------
extern "C" void kernel_launch(void* const* d_in, const int* in_sizes, int n_in,
                              void* d_out, int out_size) {
    const float* x = nullptr;
    const float* W = nullptr;
    const float* alpha = nullptr;
    const float* beta = nullptr;
    for (int i = 0; i < n_in; i++) {
        if (in_sizes[i] == TT * CC)                x = (const float*)d_in[i];
        else if (in_sizes[i] == (2 * CC + 1) * CC) W = (const float*)d_in[i];
        else if (in_sizes[i] == 1) {
            if (!alpha) alpha = (const float*)d_in[i];
            else        beta  = (const float*)d_in[i];
        }
    }
    float* out = (float*)d_out;

    k_qlast<<<256, 128>>>(x, W);          // W_q GEMV (4 MB), 1024 warps
    k_upart<<<128, 128>>>(W);             // W_k^T partials (4 MB)
    k_att  <<<NROWS / 8, 256>>>(x, W);    // u-reduce + tail dual GEMV (0.5 MB)
    k_final<<<1, BLK>>>(x, W, alpha, beta, out);
}

// round 5
// speedup vs baseline: 1.8520x; 1.1233x over previous
#include <cuda_runtime.h>
#include <cstdint>

#define TT 16384
#define CC 1024
#define NROWS 128           // tail rows in the stats table (window provably ~19)
#define N_ITERS 30
#define NPART 32            // i-chunks for u partial sums
#define GRID 148            // exactly one wave on GB300 (148+ SMs) -> safe grid barrier
#define NTH 256

__device__ float g_qlast[CC];
__device__ float g_upart[NPART * CC];
__device__ float g_u[CC];
__device__ float g_att[NROWS];
__device__ float g_av[NROWS];
__device__ int   g_barc[3];     // grid-barrier counters; left at 0 after every launch

#define SCALE 3.125e-5f     // 0.001 / sqrt(1024)

__device__ __forceinline__ float neg_inf() { return __int_as_float(0xff800000); }

// --- software grid barrier (one-wave grid; counters reset by block 0 at end) ---
__device__ __forceinline__ void gbar_arrive(int ph) {
    __syncthreads();                       // all prior work in this block done
    if (threadIdx.x == 0) {
        __threadfence();                   // release
        atomicAdd(&g_barc[ph], 1);
    }
}
__device__ __forceinline__ void gbar_wait(int ph) {
    if (threadIdx.x == 0) {
        while (*(volatile int*)&g_barc[ph] < GRID) { }
        __threadfence();                   // acquire
    }
    __syncthreads();
}

__device__ __forceinline__ float wred_sum(float v) {
#pragma unroll
    for (int o = 16; o; o >>= 1) v += __shfl_xor_sync(0xffffffffu, v, o);
    return v;
}

__global__ void __launch_bounds__(NTH, 1)
k_all(const float* __restrict__ x, const float* __restrict__ W,
      const float* __restrict__ alpha, const float* __restrict__ beta,
      float* __restrict__ out)
{
    __shared__ float su[CC];
    __shared__ float sS[NROWS + 1], sB[NROWS + 1], sY[NROWS + 1];
    __shared__ float red[8];
    __shared__ float fm[8], fs[8], fb[8], fy[8];
    __shared__ float smax;

    const int b = blockIdx.x, t = threadIdx.x;
    const int lane = t & 31, wid = t >> 5;

    // ======== STAGE 1: q_last GEMV (blocks 0-127) || av tail GEMV (128-143) ====
    if (b < 128) {
        int r = b * 8 + wid;                       // W_q row 0..1023
        const float4* xl = (const float4*)(x + (size_t)(TT - 1) * CC);
        const float4* wr = (const float4*)(W + (size_t)r * CC);
        float s = 0.f;
#pragma unroll
        for (int c = 0; c < 8; c++) {
            float4 a = xl[c * 32 + lane];
            float4 w4 = wr[c * 32 + lane];
            s += a.x * w4.x + a.y * w4.y + a.z * w4.z + a.w * w4.w;
        }
        s = wred_sum(s);
        if (lane == 0) g_qlast[r] = s;
    } else if (b < 144) {
        int l = (b - 128) * 8 + wid;               // tail distance 0..127
        const float4* xr = (const float4*)(x + (size_t)(TT - 1 - l) * CC);
        const float4* wv = (const float4*)(W + (size_t)(2 * CC) * CC);
        float s = 0.f;
#pragma unroll
        for (int c = 0; c < 8; c++) {
            float4 a = xr[c * 32 + lane];
            float4 w4 = wv[c * 32 + lane];
            s += a.x * w4.x + a.y * w4.y + a.z * w4.z + a.w * w4.w;
        }
        s = wred_sum(s);
        if (lane == 0) g_av[l] = s;
    }
    gbar_arrive(0); gbar_wait(0);

    // ======== STAGE 2: u partials over W_k (blocks 0-127) ======================
    if (b < 128) {
        int ic = b >> 2;                           // 0..31
        int jc = b & 3;
        int j  = jc * 256 + t;
        const float* Wk = W + (size_t)CC * CC;
        int i0 = ic * (CC / NPART);                // 32 i's per chunk
        float s = 0.f;
#pragma unroll
        for (int i = 0; i < CC / NPART; i++)
            s += g_qlast[i0 + i] * Wk[(size_t)(i0 + i) * CC + j];
        g_upart[ic * CC + j] = s;
    }
    gbar_arrive(1); gbar_wait(1);

    // ======== STAGE 3: tail att (blocks 0-15), g_u materialize (block 16) ======
    if (b < 16) {
#pragma unroll
        for (int c = 0; c < 4; c++) {
            int j = c * 256 + t;
            float s = 0.f;
#pragma unroll
            for (int p = 0; p < NPART; p++) s += g_upart[p * CC + j];
            su[j] = s;
        }
        __syncthreads();
        int l = b * 8 + wid;                       // 0..127
        const float4* xr  = (const float4*)(x + (size_t)(TT - 1 - l) * CC);
        const float4* su4 = (const float4*)su;
        float du = 0.f;
#pragma unroll
        for (int c = 0; c < 8; c++) {
            float4 a = xr[c * 32 + lane];
            float4 u4 = su4[c * 32 + lane];
            du += a.x * u4.x + a.y * u4.y + a.z * u4.z + a.w * u4.w;
        }
        du = wred_sum(du);
        if (lane == 0) g_att[l] = (l == 0) ? neg_inf() : du * SCALE;
    } else if (b == 16) {
#pragma unroll
        for (int c = 0; c < 4; c++) {
            int j = c * 256 + t;
            float s = 0.f;
#pragma unroll
            for (int p = 0; p < NPART; p++) s += g_upart[p * CC + j];
            g_u[j] = s;                            // for the (never-taken) fallback
        }
    }
    gbar_arrive(2);
    if (b != 0) return;                            // everyone else is done
    gbar_wait(2);
    if (t == 0) { g_barc[0] = 0; g_barc[1] = 0; g_barc[2] = 0; }   // replay-safe

    // ======== STAGE 4 (block 0 only): stats table + serial recurrence =========
    float a0 = 0.f, v0 = 0.f;
    if (t < NROWS) { a0 = g_att[t]; v0 = g_av[t]; }

    // global max over the 128 tail atts
    float lm = (t < NROWS) ? a0 : neg_inf();
#pragma unroll
    for (int o = 16; o; o >>= 1) lm = fmaxf(lm, __shfl_xor_sync(0xffffffffu, lm, o));
    if (lane == 0) red[wid] = lm;
    __syncthreads();
    if (t == 0) {
        float m0 = red[0];
#pragma unroll
        for (int i = 1; i < 8; i++) m0 = fmaxf(m0, red[i]);
        smax = m0;
    }
    __syncthreads();
    const float m = smax;

    // prefix scan of (e, e*l, e*av) over the 128 tail positions (warps 0-3)
    if (t < NROWS) {
        float e0 = expf(a0 - m);
        float ps = e0, pb = e0 * (float)t, py = e0 * v0;
#pragma unroll
        for (int o = 1; o < 32; o <<= 1) {
            float ts = __shfl_up_sync(0xffffffffu, ps, o);
            float tb = __shfl_up_sync(0xffffffffu, pb, o);
            float ty = __shfl_up_sync(0xffffffffu, py, o);
            if (lane >= o) { ps += ts; pb += tb; py += ty; }
        }
        if (lane == 31) { fs[wid] = ps; fb[wid] = pb; fy[wid] = py; }
        __syncthreads();
        if (t == 0) {
            float cs = 0.f, cb = 0.f, cy = 0.f;
#pragma unroll
            for (int i = 0; i < 4; i++) {
                float ns = fs[i], nb = fb[i], ny = fy[i];
                fs[i] = cs; fb[i] = cb; fy[i] = cy;
                cs += ns; cb += nb; cy += ny;
            }
        }
        __syncthreads();
        ps += fs[wid]; pb += fb[wid]; py += fy[wid];
        sS[t + 1] = ps; sB[t + 1] = pb; sY[t + 1] = py;
        if (t == 0) { sS[0] = 0.f; sB[0] = 0.f; sY[0] = 0.f; }
    } else {
        __syncthreads(); __syncthreads();
    }
    __syncthreads();

    // serial 30-iteration recurrence (all 256 threads redundantly)
    float a = *alpha, bb = *beta, k_old = 0.f, y = 0.f;
    for (int it = 0; it < N_ITERS; it++) {
        float kk = 2.f * (a + bb) / a;
        float wf = ceilf(kk);
        int w = (wf >= (float)TT) ? TT : (int)wf;
        if (w < 1) w = 1;

        float s, bs, ys;
        if (w <= NROWS) {
            s = sS[w]; bs = sB[w]; ys = sY[w];
        } else {
            // exact deep fallback (never taken for these inputs): online softmax
            const float4* u4  = (const float4*)g_u;
            const float4* wv4 = (const float4*)(W + (size_t)(2 * CC) * CC);
            float m_r = neg_inf(), s_r = 0.f, b_r = 0.f, y_r = 0.f;
            for (int l = wid; l < w; l += 8) {
                if (l == 0) continue;              // masked position
                const float4* xr = (const float4*)(x + (size_t)(TT - 1 - l) * CC);
                float du = 0.f, dv = 0.f;
                for (int c = 0; c < 8; c++) {
                    float4 xa = xr[c * 32 + lane];
                    float4 ub = u4[c * 32 + lane];
                    float4 vb = wv4[c * 32 + lane];
                    du += xa.x * ub.x + xa.y * ub.y + xa.z * ub.z + xa.w * ub.w;
                    dv += xa.x * vb.x + xa.y * vb.y + xa.z * vb.z + xa.w * vb.w;
                }
                du = wred_sum(du); dv = wred_sum(dv);
                float att = du * SCALE;
                float mn = fmaxf(m_r, att);
                float ro = expf(m_r - mn);
                float e  = expf(att - mn);
                s_r = s_r * ro + e;
                b_r = b_r * ro + e * (float)l;
                y_r = y_r * ro + e * dv;
                m_r = mn;
            }
            if (lane == 0) { fm[wid] = m_r; fs[wid] = s_r; fb[wid] = b_r; fy[wid] = y_r; }
            __syncthreads();
            float M = fm[0];
            for (int i = 1; i < 8; i++) M = fmaxf(M, fm[i]);
            s = 0.f; bs = 0.f; ys = 0.f;
            for (int i = 0; i < 8; i++) {
                float r2 = expf(fm[i] - M);
                s  += fs[i] * r2;
                bs += fb[i] * r2;
                ys += fy[i] * r2;
            }
            __syncthreads();
        }

        float bu = bs / s;
        y = ys / s;
        a += 1.f;
        bb += bu;
        bool stop = (kk > (float)TT) || (kk < k_old);
        k_old = kk;
        if (stop) break;
    }
    if (t == 0) out[0] = y;
}

// ---------------------------------------------------------------------------
extern "C" void kernel_launch(void* const* d_in, const int* in_sizes, int n_in,
                              void* d_out, int out_size) {
    const float* x = nullptr;
    const float* W = nullptr;
    const float* alpha = nullptr;
    const float* beta = nullptr;
    for (int i = 0; i < n_in; i++) {
        if (in_sizes[i] == TT * CC)                x = (const float*)d_in[i];
        else if (in_sizes[i] == (2 * CC + 1) * CC) W = (const float*)d_in[i];
        else if (in_sizes[i] == 1) {
            if (!alpha) alpha = (const float*)d_in[i];
            else        beta  = (const float*)d_in[i];
        }
    }
    float* out = (float*)d_out;
    k_all<<<GRID, NTH>>>(x, W, alpha, beta, out);
}